// round 5
// baseline (speedup 1.0000x reference)
#include <cuda_runtime.h>
#include <cstdint>

#define NCTX 4096
#define DM   512
#define NB   2
#define LDKT (NB*NCTX)

// Scratch (tf32 hi/lo decompositions + transposed K + scores)
__device__ float g_xhi[(size_t)NB*NCTX*DM];
__device__ float g_xlo[(size_t)NB*NCTX*DM];
__device__ float g_Whi[(size_t)DM*DM];
__device__ float g_Wlo[(size_t)DM*DM];
__device__ float g_Khi[(size_t)NB*NCTX*DM];
__device__ float g_Klo[(size_t)NB*NCTX*DM];
__device__ float g_Kt [(size_t)DM*NB*NCTX];   // tf32-rounded K^T
__device__ float g_S  [(size_t)NB*NCTX*NCTX]; // scores / probs

// ---------------------------------------------------------------------------
// helpers
// ---------------------------------------------------------------------------
__device__ __forceinline__ uint32_t s2u(const void* p){
  uint32_t a;
  asm("{ .reg .u64 t; cvta.to.shared.u64 t, %1; cvt.u32.u64 %0, t; }" : "=r"(a) : "l"(p));
  return a;
}
__device__ __forceinline__ float tf32r(float x){
  uint32_t u; asm("cvt.rna.tf32.f32 %0, %1;" : "=r"(u) : "f"(x));
  return __uint_as_float(u);
}
__device__ __forceinline__ void ldsm4(uint32_t* r, uint32_t addr){
  asm volatile("ldmatrix.sync.aligned.m8n8.x4.shared.b16 {%0,%1,%2,%3}, [%4];"
    : "=r"(r[0]), "=r"(r[1]), "=r"(r[2]), "=r"(r[3]) : "r"(addr));
}
__device__ __forceinline__ void mma8(float* c, const uint32_t* a, const uint32_t* b){
  asm volatile("mma.sync.aligned.m16n8k8.row.col.f32.tf32.tf32.f32 "
    "{%0,%1,%2,%3}, {%4,%5,%6,%7}, {%8,%9}, {%0,%1,%2,%3};"
    : "+f"(c[0]), "+f"(c[1]), "+f"(c[2]), "+f"(c[3])
    : "r"(a[0]), "r"(a[1]), "r"(a[2]), "r"(a[3]), "r"(b[0]), "r"(b[1]));
}
__device__ __forceinline__ void cp16(uint32_t d, const void* s){
  asm volatile("cp.async.cg.shared.global [%0], [%1], 16;" :: "r"(d), "l"(s));
}
__device__ __forceinline__ void cp_commit(){
  asm volatile("cp.async.commit_group;" ::: "memory");
}
template<int N> __device__ __forceinline__ void cp_wait(){
  asm volatile("cp.async.wait_group %0;" :: "n"(N) : "memory");
}

// ---------------------------------------------------------------------------
// Async tf32 GEMM: C[128x128 tile] = A[m0:,k0:k1] * B[n0:,k0:k1]^T
// Inputs are PRE-DECOMPOSED tf32 arrays (hi/lo for SPLIT, hi only otherwise).
// cp.async multi-stage pipeline; smem rows padded to 20 floats.
// ---------------------------------------------------------------------------
#define TILE_B  (128*20*4)      // one operand tile: 10240 B
#define MFRAG_B (16*20*4)

template<bool SPLIT, int STAGES, class EPI>
__device__ __forceinline__ void tc_gemm(
    const float* __restrict__ Ah, const float* __restrict__ Al, int lda,
    const float* __restrict__ Bh, const float* __restrict__ Bl, int ldb,
    int m0, int n0, int k0, int k1, EPI&& epi)
{
  extern __shared__ __align__(16) char sd[];
  const int NT    = SPLIT ? 4 : 2;
  const int STAGE = NT * TILE_B;
  const int t = threadIdx.x, l = t & 31, w = t >> 5;
  const int wm = w & 3, wn = w >> 2;
  const int arow = t >> 1, acol = (t & 1) * 8;
  const uint32_t soff = (uint32_t)(arow*20 + acol) * 4;
  const uint32_t sb = s2u(sd);

  const float* pAh = Ah + (size_t)(m0 + arow)*lda + acol;
  const float* pAl = SPLIT ? Al + (size_t)(m0 + arow)*lda + acol : pAh;
  const float* pBh = Bh + (size_t)(n0 + arow)*ldb + acol;
  const float* pBl = SPLIT ? Bl + (size_t)(n0 + arow)*ldb + acol : pBh;

  const int nch = (k1 - k0) >> 4;

  auto load_stage = [&](int c){
    const int kb = k0 + (c << 4);
    const uint32_t st  = sb + (c % STAGES)*STAGE + soff;
    const uint32_t stB = st + (SPLIT ? 2 : 1)*TILE_B;
    cp16(st,       pAh + kb);  cp16(st  + 16, pAh + kb + 4);
    cp16(stB,      pBh + kb);  cp16(stB + 16, pBh + kb + 4);
    if (SPLIT){
      cp16(st  + TILE_B,      pAl + kb);  cp16(st  + TILE_B + 16, pAl + kb + 4);
      cp16(stB + TILE_B,      pBl + kb);  cp16(stB + TILE_B + 16, pBl + kb + 4);
    }
  };

  #pragma unroll
  for (int s = 0; s < STAGES-1; s++){
    if (s < nch) load_stage(s);
    cp_commit();
  }

  // ldmatrix per-lane offsets
  const int rowA = (l & 7) + ((l >> 3) & 1) * 8;
  const int colA = ((l >> 4) & 1) * 4;
  const int rowB = (l & 7) + ((l >> 4) & 1) * 8;
  const int colB = ((l >> 3) & 1) * 4;
  const uint32_t aoff = (uint32_t)((wm*32 + rowA)*20 + colA) * 4;
  const uint32_t boff = (uint32_t)((wn*64 + rowB)*20 + colB) * 4;

  float acc[2][8][4] = {};

  for (int c = 0; c < nch; c++){
    cp_wait<STAGES-2>();
    __syncthreads();
    const int cn = c + STAGES - 1;
    if (cn < nch) load_stage(cn);
    cp_commit();

    const uint32_t base = sb + (c % STAGES)*STAGE;
    const uint32_t uAhi = base + aoff;
    const uint32_t uAlo = uAhi + TILE_B;
    const uint32_t uBhi = base + (SPLIT ? 2 : 1)*TILE_B + boff;
    const uint32_t uBlo = uBhi + TILE_B;

    #pragma unroll
    for (int kf = 0; kf < 2; kf++){
      const uint32_t ko = kf * 32;
      uint32_t ah[2][4], al[2][4];
      ldsm4(ah[0], uAhi + ko);
      ldsm4(ah[1], uAhi + ko + MFRAG_B);
      if (SPLIT){
        ldsm4(al[0], uAlo + ko);
        ldsm4(al[1], uAlo + ko + MFRAG_B);
      }
      #pragma unroll
      for (int nf2 = 0; nf2 < 4; nf2++){
        uint32_t bh[4];
        ldsm4(bh, uBhi + ko + nf2 * MFRAG_B);
        #pragma unroll
        for (int mf = 0; mf < 2; mf++){
          mma8(acc[mf][2*nf2],     ah[mf], bh);
          mma8(acc[mf][2*nf2 + 1], ah[mf], bh + 2);
        }
        if (SPLIT){
          uint32_t bl[4];
          ldsm4(bl, uBlo + ko + nf2 * MFRAG_B);
          #pragma unroll
          for (int mf = 0; mf < 2; mf++){
            mma8(acc[mf][2*nf2],     ah[mf], bl);
            mma8(acc[mf][2*nf2 + 1], ah[mf], bl + 2);
            mma8(acc[mf][2*nf2],     al[mf], bh);
            mma8(acc[mf][2*nf2 + 1], al[mf], bh + 2);
          }
        }
      }
    }
  }
  epi(acc);
}

// plain store epilogue
__device__ __forceinline__ void epi_store(float (&acc)[2][8][4],
                                          float* __restrict__ C, int ldc,
                                          int m0, int n0)
{
  const int t = threadIdx.x, l = t & 31, w = t >> 5;
  const int wm = w & 3, wn = w >> 2;
  #pragma unroll
  for (int mf = 0; mf < 2; mf++){
    const int r0 = m0 + wm*32 + mf*16 + (l >> 2);
    #pragma unroll
    for (int nf = 0; nf < 8; nf++){
      const int cc = n0 + wn*64 + nf*8 + 2*(l & 3);
      *(float2*)&C[(size_t)r0*ldc + cc]     = make_float2(acc[mf][nf][0], acc[mf][nf][1]);
      *(float2*)&C[(size_t)(r0+8)*ldc + cc] = make_float2(acc[mf][nf][2], acc[mf][nf][3]);
    }
  }
}

// ---------------------------------------------------------------------------
// Kernels
// ---------------------------------------------------------------------------
__global__ void __launch_bounds__(256)
k_prep(const float* __restrict__ x, const float* __restrict__ W)
{ // hi/lo decomposition of x and W (float4 grid-stride)
  const size_t nx = (size_t)NB*NCTX*DM/4, nw = (size_t)DM*DM/4;
  for (size_t i = blockIdx.x*256 + threadIdx.x; i < nx + nw; i += (size_t)gridDim.x*256){
    if (i < nx){
      float4 v = ((const float4*)x)[i];
      float4 h = make_float4(tf32r(v.x), tf32r(v.y), tf32r(v.z), tf32r(v.w));
      ((float4*)g_xhi)[i] = h;
      ((float4*)g_xlo)[i] = make_float4(tf32r(v.x-h.x), tf32r(v.y-h.y),
                                        tf32r(v.z-h.z), tf32r(v.w-h.w));
    } else {
      size_t j = i - nx;
      float4 v = ((const float4*)W)[j];
      float4 h = make_float4(tf32r(v.x), tf32r(v.y), tf32r(v.z), tf32r(v.w));
      ((float4*)g_Whi)[j] = h;
      ((float4*)g_Wlo)[j] = make_float4(tf32r(v.x-h.x), tf32r(v.y-h.y),
                                        tf32r(v.z-h.z), tf32r(v.w-h.w));
    }
  }
}

__global__ void __launch_bounds__(256, 2)
k_proj()
{ // K = x @ W^T -> writes Khi/Klo and tf32-rounded Kt
  const int n0 = blockIdx.x*128, m0 = blockIdx.y*128;
  tc_gemm<true, 2>(g_xhi, g_xlo, DM, g_Whi, g_Wlo, DM, m0, n0, 0, DM,
    [&](float (&acc)[2][8][4]){
      const int t = threadIdx.x, l = t & 31, w = t >> 5;
      const int wm = w & 3, wn = w >> 2;
      #pragma unroll
      for (int mf = 0; mf < 2; mf++){
        const int r0 = m0 + wm*32 + mf*16 + (l >> 2);
        #pragma unroll
        for (int nf = 0; nf < 8; nf++){
          const int cc = n0 + wn*64 + nf*8 + 2*(l & 3);
          #pragma unroll
          for (int hh = 0; hh < 2; hh++){   // row r0 and r0+8
            const int r = r0 + hh*8;
            float v0 = acc[mf][nf][2*hh], v1 = acc[mf][nf][2*hh+1];
            float h0 = tf32r(v0), h1 = tf32r(v1);
            const size_t ki = (size_t)r*DM + cc;
            *(float2*)&g_Khi[ki] = make_float2(h0, h1);
            *(float2*)&g_Klo[ki] = make_float2(tf32r(v0-h0), tf32r(v1-h1));
            g_Kt[(size_t)cc    *LDKT + r] = h0;
            g_Kt[(size_t)(cc+1)*LDKT + r] = h1;
          }
        }
      }
    });
}

__global__ void __launch_bounds__(256, 2)
k_scores()
{ // S = x @ K^T (lower-triangular tiles)
  const int b  = blockIdx.z;
  const int n0 = blockIdx.x*128, m0 = blockIdx.y*128;
  if (n0 > m0) return;
  const size_t off = (size_t)b*NCTX*DM;
  float* Sb = g_S + (size_t)b*NCTX*NCTX;
  tc_gemm<true, 2>(g_xhi + off, g_xlo + off, DM, g_Khi + off, g_Klo + off, DM,
    m0, n0, 0, DM,
    [&](float (&acc)[2][8][4]){ epi_store(acc, Sb, NCTX, m0, n0); });
}

__global__ void __launch_bounds__(256, 2)
k_out_tc(const float* __restrict__ x, float* __restrict__ out)
{ // out = x + P @ K  (split-K over causal extent)
  const int b = blockIdx.z >> 2, cch = blockIdx.z & 3;
  const int n0 = blockIdx.x*128, m0 = blockIdx.y*128;
  const int kend = m0 + 128, kbeg = cch*1024;
  if (kbeg >= kend) return;
  const int k1 = kend < kbeg + 1024 ? kend : kbeg + 1024;
  const bool single = (kend <= 1024);   // only chunk 0 exists for this tile
  const float* Pb = g_S  + (size_t)b*NCTX*NCTX;
  const float* Bt = g_Kt + (size_t)b*NCTX;
  tc_gemm<false, 4>(Pb, nullptr, NCTX, Bt, nullptr, LDKT, m0, n0, kbeg, k1,
    [&](float (&acc)[2][8][4]){
      const int t = threadIdx.x, l = t & 31, w = t >> 5;
      const int wm = w & 3, wn = w >> 2;
      #pragma unroll
      for (int mf = 0; mf < 2; mf++){
        const int r0 = m0 + wm*32 + mf*16 + (l >> 2);
        #pragma unroll
        for (int nf = 0; nf < 8; nf++){
          const int cc = n0 + wn*64 + nf*8 + 2*(l & 3);
          const size_t i0 = (size_t)b*NCTX*DM + (size_t)r0*DM + cc;
          const size_t i1 = i0 + (size_t)8*DM;
          float v0 = acc[mf][nf][0], v1 = acc[mf][nf][1];
          float v2 = acc[mf][nf][2], v3 = acc[mf][nf][3];
          if (single){
            *(float2*)&out[i0] = make_float2(v0 + x[i0], v1 + x[i0+1]);
            *(float2*)&out[i1] = make_float2(v2 + x[i1], v3 + x[i1+1]);
          } else {
            if (cch == 0){ v0 += x[i0]; v1 += x[i0+1]; v2 += x[i1]; v3 += x[i1+1]; }
            atomicAdd(out + i0,     v0);
            atomicAdd(out + i0 + 1, v1);
            atomicAdd(out + i1,     v2);
            atomicAdd(out + i1 + 1, v3);
          }
        }
      }
    });
}

// ---------------------------------------------------------------------------
// Causal softmax, in place on g_S; final P is tf32-rounded.
// ---------------------------------------------------------------------------
__device__ __forceinline__ float blk_reduce(float v, bool is_max)
{
  __shared__ float sm[8];
  const int lane = threadIdx.x & 31, w = threadIdx.x >> 5;
  #pragma unroll
  for (int o = 16; o; o >>= 1){
    float u = __shfl_xor_sync(0xffffffffu, v, o);
    v = is_max ? fmaxf(v, u) : v + u;
  }
  if (lane == 0) sm[w] = v;
  __syncthreads();
  float r = sm[0];
  #pragma unroll
  for (int i = 1; i < 8; i++) r = is_max ? fmaxf(r, sm[i]) : r + sm[i];
  __syncthreads();
  return r;
}

__global__ void __launch_bounds__(256)
k_softmax()
{
  const int row = blockIdx.x;
  const int q   = row & (NCTX - 1);
  float* p = g_S + (size_t)row * NCTX;
  const int len  = q + 1;
  const int len4 = len >> 2;
  float4* p4 = (float4*)p;

  float m = -1e30f;
  for (int i = threadIdx.x; i < len4; i += 256){
    float4 v = p4[i];
    m = fmaxf(m, fmaxf(fmaxf(v.x, v.y), fmaxf(v.z, v.w)));
  }
  for (int i = (len4 << 2) + threadIdx.x; i < len; i += 256) m = fmaxf(m, p[i]);
  m = blk_reduce(m, true);

  float s = 0.f;
  for (int i = threadIdx.x; i < len4; i += 256){
    float4 v = p4[i];
    v.x = __expf(v.x - m); v.y = __expf(v.y - m);
    v.z = __expf(v.z - m); v.w = __expf(v.w - m);
    p4[i] = v;
    s += (v.x + v.y) + (v.z + v.w);
  }
  for (int i = (len4 << 2) + threadIdx.x; i < len; i += 256){
    float e = __expf(p[i] - m);
    p[i] = e;
    s += e;
  }
  s = blk_reduce(s, false);
  const float inv = 1.f / s;

  for (int i = threadIdx.x; i < len4; i += 256){
    float4 v = p4[i];
    v.x = tf32r(v.x * inv); v.y = tf32r(v.y * inv);
    v.z = tf32r(v.z * inv); v.w = tf32r(v.w * inv);
    p4[i] = v;
  }
  for (int i = (len4 << 2) + threadIdx.x; i < len; i += 256) p[i] = tf32r(p[i] * inv);

  const int lenUp = (len + 127) & ~127;
  for (int i = len + threadIdx.x; i < lenUp; i += 256) p[i] = 0.f;
}

// ---------------------------------------------------------------------------
extern "C" void kernel_launch(void* const* d_in, const int* in_sizes, int n_in,
                              void* d_out, int out_size)
{
  const float* x = (const float*)d_in[0];
  const float* W = (const float*)d_in[1];
  float* out = (float*)d_out;

  const int SMEM_SPLIT = 2 * 4 * TILE_B;   // 81920 (2 stages x 4 tiles)
  const int SMEM_PLAIN = 4 * 2 * TILE_B;   // 81920 (4 stages x 2 tiles)
  cudaFuncSetAttribute(k_proj,    cudaFuncAttributeMaxDynamicSharedMemorySize, SMEM_SPLIT);
  cudaFuncSetAttribute(k_scores,  cudaFuncAttributeMaxDynamicSharedMemorySize, SMEM_SPLIT);
  cudaFuncSetAttribute(k_out_tc,  cudaFuncAttributeMaxDynamicSharedMemorySize, SMEM_PLAIN);

  cudaMemsetAsync(out, 0, (size_t)out_size * sizeof(float), 0);

  k_prep   <<<1184, 256>>>(x, W);
  k_proj   <<<dim3(4, 64),       256, SMEM_SPLIT>>>();
  k_scores <<<dim3(32, 32, NB),  256, SMEM_SPLIT>>>();
  k_softmax<<<NB * NCTX, 256>>>();
  k_out_tc <<<dim3(4, 32, NB*4), 256, SMEM_PLAIN>>>(x, out);
}

// round 6
// speedup vs baseline: 1.5024x; 1.5024x over previous
#include <cuda_runtime.h>
#include <cuda_bf16.h>
#include <cstdint>

#define NCTX 4096
#define DM   512
#define NB   2
#define LDKT (NB*NCTX)

// Scratch
__device__ __nv_bfloat16 g_xhi[(size_t)NB*NCTX*DM];
__device__ __nv_bfloat16 g_xlo[(size_t)NB*NCTX*DM];
__device__ __nv_bfloat16 g_Whi[(size_t)DM*DM];
__device__ __nv_bfloat16 g_Wlo[(size_t)DM*DM];
__device__ __nv_bfloat16 g_Khi[(size_t)NB*NCTX*DM];
__device__ __nv_bfloat16 g_Klo[(size_t)NB*NCTX*DM];
__device__ float g_Kt[(size_t)DM*NB*NCTX];    // tf32-rounded K^T (fp32 storage)
__device__ float g_S [(size_t)NB*NCTX*NCTX];  // scores / probs

// ---------------------------------------------------------------------------
// helpers
// ---------------------------------------------------------------------------
__device__ __forceinline__ uint32_t s2u(const void* p){
  uint32_t a;
  asm("{ .reg .u64 t; cvta.to.shared.u64 t, %1; cvt.u32.u64 %0, t; }" : "=r"(a) : "l"(p));
  return a;
}
__device__ __forceinline__ float tf32r(float x){
  uint32_t u; asm("cvt.rna.tf32.f32 %0, %1;" : "=r"(u) : "f"(x));
  return __uint_as_float(u);
}
__device__ __forceinline__ void ldsm4(uint32_t* r, uint32_t addr){
  asm volatile("ldmatrix.sync.aligned.m8n8.x4.shared.b16 {%0,%1,%2,%3}, [%4];"
    : "=r"(r[0]), "=r"(r[1]), "=r"(r[2]), "=r"(r[3]) : "r"(addr));
}
__device__ __forceinline__ void mma8(float* c, const uint32_t* a, const uint32_t* b){
  asm volatile("mma.sync.aligned.m16n8k8.row.col.f32.tf32.tf32.f32 "
    "{%0,%1,%2,%3}, {%4,%5,%6,%7}, {%8,%9}, {%0,%1,%2,%3};"
    : "+f"(c[0]), "+f"(c[1]), "+f"(c[2]), "+f"(c[3])
    : "r"(a[0]), "r"(a[1]), "r"(a[2]), "r"(a[3]), "r"(b[0]), "r"(b[1]));
}
__device__ __forceinline__ void bmma(float* c, const uint32_t* a, const uint32_t* b){
  asm volatile("mma.sync.aligned.m16n8k16.row.col.f32.bf16.bf16.f32 "
    "{%0,%1,%2,%3}, {%4,%5,%6,%7}, {%8,%9}, {%0,%1,%2,%3};"
    : "+f"(c[0]), "+f"(c[1]), "+f"(c[2]), "+f"(c[3])
    : "r"(a[0]), "r"(a[1]), "r"(a[2]), "r"(a[3]), "r"(b[0]), "r"(b[1]));
}
__device__ __forceinline__ void cp16(uint32_t d, const void* s){
  asm volatile("cp.async.cg.shared.global [%0], [%1], 16;" :: "r"(d), "l"(s));
}
__device__ __forceinline__ void cp_commit(){
  asm volatile("cp.async.commit_group;" ::: "memory");
}
template<int N> __device__ __forceinline__ void cp_wait(){
  asm volatile("cp.async.wait_group %0;" :: "n"(N) : "memory");
}

// ===========================================================================
// bf16 split (3-MMA) GEMM: C[128x128] = A * B^T, A:[M,K] bf16 hi/lo,
// B:[N,K] bf16 hi/lo, both row-major K-major. BK=32. 256 threads, 2 stages.
// smem row pitch 80B (32 bf16 data + pad) -> conflict-free ldmatrix.
// ===========================================================================
#define BT_TILE  10240            // 128 rows * 80 B
#define BT_STAGE (4*BT_TILE)      // Ahi,Alo,Bhi,Blo

template<class EPI>
__device__ __forceinline__ void bgemm_split(
    const __nv_bfloat16* __restrict__ Ah, const __nv_bfloat16* __restrict__ Al, int lda,
    const __nv_bfloat16* __restrict__ Bh, const __nv_bfloat16* __restrict__ Bl, int ldb,
    int m0, int n0, int k1, EPI&& epi)
{
  extern __shared__ __align__(16) char sd[];
  const int t = threadIdx.x, l = t & 31, w = t >> 5;
  const int wm = w & 3, wn = w >> 2;
  const int row = t >> 1, seg = (t & 1) * 16;    // 16 bf16 = 32 B half-row
  const uint32_t sb = s2u(sd);
  const uint32_t soff = (uint32_t)row*80 + (t & 1)*32;

  const __nv_bfloat16* pAh = Ah + (size_t)(m0 + row)*lda + seg;
  const __nv_bfloat16* pAl = Al + (size_t)(m0 + row)*lda + seg;
  const __nv_bfloat16* pBh = Bh + (size_t)(n0 + row)*ldb + seg;
  const __nv_bfloat16* pBl = Bl + (size_t)(n0 + row)*ldb + seg;

  const int nch = k1 >> 5;
  auto load_stage = [&](int c){
    const int kb = c << 5;
    const uint32_t st = sb + (c & 1)*BT_STAGE + soff;
    cp16(st,               pAh + kb); cp16(st + 16,             pAh + kb + 8);
    cp16(st +   BT_TILE,   pAl + kb); cp16(st +   BT_TILE + 16, pAl + kb + 8);
    cp16(st + 2*BT_TILE,   pBh + kb); cp16(st + 2*BT_TILE + 16, pBh + kb + 8);
    cp16(st + 3*BT_TILE,   pBl + kb); cp16(st + 3*BT_TILE + 16, pBl + kb + 8);
  };
  load_stage(0);
  cp_commit();

  // fragment offsets (bf16, pitch 80B)
  const uint32_t aoff = (uint32_t)(wm*32 + (l & 15))*80 + ((l >> 4) & 1)*16;
  const uint32_t boff = (uint32_t)(wn*64 + (l & 7) + ((l >> 4) & 1)*8)*80
                      + ((l >> 3) & 1)*16;

  float acc[2][8][4] = {};

  for (int c = 0; c < nch; c++){
    cp_wait<0>();
    __syncthreads();
    if (c + 1 < nch) load_stage(c + 1);
    cp_commit();

    const uint32_t base = sb + (c & 1)*BT_STAGE;
    const uint32_t uAh = base + aoff,            uAl = uAh + BT_TILE;
    const uint32_t uBh = base + 2*BT_TILE + boff, uBl = uBh + BT_TILE;

    #pragma unroll
    for (int kf = 0; kf < 2; kf++){
      const uint32_t ko = kf*32;                 // 16 bf16 = 32 B
      uint32_t ah[2][4], al[2][4];
      ldsm4(ah[0], uAh + ko);  ldsm4(ah[1], uAh + ko + 16*80);
      ldsm4(al[0], uAl + ko);  ldsm4(al[1], uAl + ko + 16*80);
      #pragma unroll
      for (int nf2 = 0; nf2 < 4; nf2++){
        uint32_t bh[4], bl[4];
        ldsm4(bh, uBh + ko + nf2*16*80);
        ldsm4(bl, uBl + ko + nf2*16*80);
        #pragma unroll
        for (int mf = 0; mf < 2; mf++){
          bmma(acc[mf][2*nf2],     ah[mf], bh);
          bmma(acc[mf][2*nf2 + 1], ah[mf], bh + 2);
          bmma(acc[mf][2*nf2],     ah[mf], bl);
          bmma(acc[mf][2*nf2 + 1], ah[mf], bl + 2);
          bmma(acc[mf][2*nf2],     al[mf], bh);
          bmma(acc[mf][2*nf2 + 1], al[mf], bh + 2);
        }
      }
    }
  }
  epi(acc);
}

// ===========================================================================
// tf32 single GEMM (for P @ K), fp32 inputs, 4-stage cp.async. BK=16.
// smem rows padded to 20 floats.
// ===========================================================================
#define TILE_B  (128*20*4)
#define MFRAG_B (16*20*4)

template<int STAGES, class EPI>
__device__ __forceinline__ void tgemm(
    const float* __restrict__ A, int lda,
    const float* __restrict__ B, int ldb,
    int m0, int n0, int k0, int k1, EPI&& epi)
{
  extern __shared__ __align__(16) char sd[];
  const int STAGE = 2*TILE_B;
  const int t = threadIdx.x, l = t & 31, w = t >> 5;
  const int wm = w & 3, wn = w >> 2;
  const int arow = t >> 1, acol = (t & 1) * 8;
  const uint32_t soff = (uint32_t)(arow*20 + acol) * 4;
  const uint32_t sb = s2u(sd);

  const float* pA = A + (size_t)(m0 + arow)*lda + acol;
  const float* pB = B + (size_t)(n0 + arow)*ldb + acol;

  const int nch = (k1 - k0) >> 4;
  auto load_stage = [&](int c){
    const int kb = k0 + (c << 4);
    const uint32_t st  = sb + (c % STAGES)*STAGE + soff;
    cp16(st,            pA + kb);  cp16(st + 16,          pA + kb + 4);
    cp16(st + TILE_B,   pB + kb);  cp16(st + TILE_B + 16, pB + kb + 4);
  };
  #pragma unroll
  for (int s = 0; s < STAGES-1; s++){
    if (s < nch) load_stage(s);
    cp_commit();
  }

  const int rowA = (l & 7) + ((l >> 3) & 1) * 8;
  const int colA = ((l >> 4) & 1) * 4;
  const int rowB = (l & 7) + ((l >> 4) & 1) * 8;
  const int colB = ((l >> 3) & 1) * 4;
  const uint32_t aoff = (uint32_t)((wm*32 + rowA)*20 + colA) * 4;
  const uint32_t boff = (uint32_t)((wn*64 + rowB)*20 + colB) * 4;

  float acc[2][8][4] = {};

  for (int c = 0; c < nch; c++){
    cp_wait<STAGES-2>();
    __syncthreads();
    const int cn = c + STAGES - 1;
    if (cn < nch) load_stage(cn);
    cp_commit();

    const uint32_t base = sb + (c % STAGES)*STAGE;
    const uint32_t uA = base + aoff;
    const uint32_t uB = base + TILE_B + boff;

    #pragma unroll
    for (int kf = 0; kf < 2; kf++){
      const uint32_t ko = kf * 32;
      uint32_t a[2][4];
      ldsm4(a[0], uA + ko);
      ldsm4(a[1], uA + ko + MFRAG_B);
      #pragma unroll
      for (int nf2 = 0; nf2 < 4; nf2++){
        uint32_t b[4];
        ldsm4(b, uB + ko + nf2 * MFRAG_B);
        #pragma unroll
        for (int mf = 0; mf < 2; mf++){
          mma8(acc[mf][2*nf2],     a[mf], b);
          mma8(acc[mf][2*nf2 + 1], a[mf], b + 2);
        }
      }
    }
  }
  epi(acc);
}

// plain store epilogue
__device__ __forceinline__ void epi_store(float (&acc)[2][8][4],
                                          float* __restrict__ C, int ldc,
                                          int m0, int n0)
{
  const int t = threadIdx.x, l = t & 31, w = t >> 5;
  const int wm = w & 3, wn = w >> 2;
  #pragma unroll
  for (int mf = 0; mf < 2; mf++){
    const int r0 = m0 + wm*32 + mf*16 + (l >> 2);
    #pragma unroll
    for (int nf = 0; nf < 8; nf++){
      const int cc = n0 + wn*64 + nf*8 + 2*(l & 3);
      *(float2*)&C[(size_t)r0*ldc + cc]     = make_float2(acc[mf][nf][0], acc[mf][nf][1]);
      *(float2*)&C[(size_t)(r0+8)*ldc + cc] = make_float2(acc[mf][nf][2], acc[mf][nf][3]);
    }
  }
}

// ---------------------------------------------------------------------------
// Kernels
// ---------------------------------------------------------------------------
__global__ void __launch_bounds__(256)
k_prep(const float* __restrict__ x, const float* __restrict__ W)
{ // bf16 hi/lo decomposition of x and W
  const size_t nx = (size_t)NB*NCTX*DM/4, nw = (size_t)DM*DM/4;
  for (size_t i = blockIdx.x*256 + threadIdx.x; i < nx + nw; i += (size_t)gridDim.x*256){
    float4 v;
    __nv_bfloat16* hi; __nv_bfloat16* lo; size_t j;
    if (i < nx){ v = ((const float4*)x)[i];      hi = g_xhi; lo = g_xlo; j = i; }
    else       { v = ((const float4*)W)[i - nx]; hi = g_Whi; lo = g_Wlo; j = i - nx; }
    __nv_bfloat16 hx = __float2bfloat16_rn(v.x), hy = __float2bfloat16_rn(v.y);
    __nv_bfloat16 hz = __float2bfloat16_rn(v.z), hw = __float2bfloat16_rn(v.w);
    __nv_bfloat162 h01; h01.x = hx; h01.y = hy;
    __nv_bfloat162 h23; h23.x = hz; h23.y = hw;
    __nv_bfloat162 l01; l01.x = __float2bfloat16_rn(v.x - __bfloat162float(hx));
                        l01.y = __float2bfloat16_rn(v.y - __bfloat162float(hy));
    __nv_bfloat162 l23; l23.x = __float2bfloat16_rn(v.z - __bfloat162float(hz));
                        l23.y = __float2bfloat16_rn(v.w - __bfloat162float(hw));
    ((__nv_bfloat162*)hi)[2*j]     = h01;
    ((__nv_bfloat162*)hi)[2*j + 1] = h23;
    ((__nv_bfloat162*)lo)[2*j]     = l01;
    ((__nv_bfloat162*)lo)[2*j + 1] = l23;
  }
}

__global__ void __launch_bounds__(256, 2)
k_proj()
{ // K = x @ W^T -> Khi/Klo (bf16) and tf32-rounded Kt (fp32, transposed)
  const int n0 = blockIdx.x*128, m0 = blockIdx.y*128;
  bgemm_split(g_xhi, g_xlo, DM, g_Whi, g_Wlo, DM, m0, n0, DM,
    [&](float (&acc)[2][8][4]){
      const int t = threadIdx.x, l = t & 31, w = t >> 5;
      const int wm = w & 3, wn = w >> 2;
      #pragma unroll
      for (int mf = 0; mf < 2; mf++){
        const int r0 = m0 + wm*32 + mf*16 + (l >> 2);
        #pragma unroll
        for (int nf = 0; nf < 8; nf++){
          const int cc = n0 + wn*64 + nf*8 + 2*(l & 3);
          #pragma unroll
          for (int hh = 0; hh < 2; hh++){
            const int r = r0 + hh*8;
            const float v0 = acc[mf][nf][2*hh], v1 = acc[mf][nf][2*hh+1];
            __nv_bfloat16 h0 = __float2bfloat16_rn(v0), h1 = __float2bfloat16_rn(v1);
            __nv_bfloat162 hp; hp.x = h0; hp.y = h1;
            __nv_bfloat162 lp;
            lp.x = __float2bfloat16_rn(v0 - __bfloat162float(h0));
            lp.y = __float2bfloat16_rn(v1 - __bfloat162float(h1));
            const size_t ki = (size_t)r*DM + cc;
            *(__nv_bfloat162*)&g_Khi[ki] = hp;
            *(__nv_bfloat162*)&g_Klo[ki] = lp;
            g_Kt[(size_t)cc    *LDKT + r] = tf32r(v0);
            g_Kt[(size_t)(cc+1)*LDKT + r] = tf32r(v1);
          }
        }
      }
    });
}

__global__ void __launch_bounds__(256, 2)
k_scores()
{ // S = x @ K^T (lower-triangular tiles)
  const int b  = blockIdx.z;
  const int n0 = blockIdx.x*128, m0 = blockIdx.y*128;
  if (n0 > m0) return;
  const size_t off = (size_t)b*NCTX*DM;
  float* Sb = g_S + (size_t)b*NCTX*NCTX;
  bgemm_split(g_xhi + off, g_xlo + off, DM, g_Khi + off, g_Klo + off, DM,
    m0, n0, DM,
    [&](float (&acc)[2][8][4]){ epi_store(acc, Sb, NCTX, m0, n0); });
}

__global__ void __launch_bounds__(256, 2)
k_out_tc(const float* __restrict__ x, float* __restrict__ out)
{ // out = x + P @ K (tf32 single, split-K over causal extent)
  const int b = blockIdx.z >> 2, cch = blockIdx.z & 3;
  const int n0 = blockIdx.x*128, m0 = blockIdx.y*128;
  const int kend = m0 + 128, kbeg = cch*1024;
  if (kbeg >= kend) return;
  const int k1 = kend < kbeg + 1024 ? kend : kbeg + 1024;
  const bool single = (kend <= 1024);
  const float* Pb = g_S  + (size_t)b*NCTX*NCTX;
  const float* Bt = g_Kt + (size_t)b*NCTX;
  tgemm<4>(Pb, NCTX, Bt, LDKT, m0, n0, kbeg, k1,
    [&](float (&acc)[2][8][4]){
      const int t = threadIdx.x, l = t & 31, w = t >> 5;
      const int wm = w & 3, wn = w >> 2;
      #pragma unroll
      for (int mf = 0; mf < 2; mf++){
        const int r0 = m0 + wm*32 + mf*16 + (l >> 2);
        #pragma unroll
        for (int nf = 0; nf < 8; nf++){
          const int cc = n0 + wn*64 + nf*8 + 2*(l & 3);
          const size_t i0 = (size_t)b*NCTX*DM + (size_t)r0*DM + cc;
          const size_t i1 = i0 + (size_t)8*DM;
          float v0 = acc[mf][nf][0], v1 = acc[mf][nf][1];
          float v2 = acc[mf][nf][2], v3 = acc[mf][nf][3];
          if (single){
            *(float2*)&out[i0] = make_float2(v0 + x[i0], v1 + x[i0+1]);
            *(float2*)&out[i1] = make_float2(v2 + x[i1], v3 + x[i1+1]);
          } else {
            if (cch == 0){ v0 += x[i0]; v1 += x[i0+1]; v2 += x[i1]; v3 += x[i1+1]; }
            atomicAdd(out + i0,     v0);
            atomicAdd(out + i0 + 1, v1);
            atomicAdd(out + i1,     v2);
            atomicAdd(out + i1 + 1, v3);
          }
        }
      }
    });
}

// ---------------------------------------------------------------------------
// Causal softmax, in place on g_S; final P tf32-rounded.
// ---------------------------------------------------------------------------
__device__ __forceinline__ float blk_reduce(float v, bool is_max)
{
  __shared__ float sm[8];
  const int lane = threadIdx.x & 31, w = threadIdx.x >> 5;
  #pragma unroll
  for (int o = 16; o; o >>= 1){
    float u = __shfl_xor_sync(0xffffffffu, v, o);
    v = is_max ? fmaxf(v, u) : v + u;
  }
  if (lane == 0) sm[w] = v;
  __syncthreads();
  float r = sm[0];
  #pragma unroll
  for (int i = 1; i < 8; i++) r = is_max ? fmaxf(r, sm[i]) : r + sm[i];
  __syncthreads();
  return r;
}

__global__ void __launch_bounds__(256)
k_softmax()
{
  const int row = blockIdx.x;
  const int q   = row & (NCTX - 1);
  float* p = g_S + (size_t)row * NCTX;
  const int len  = q + 1;
  const int len4 = len >> 2;
  float4* p4 = (float4*)p;

  float m = -1e30f;
  for (int i = threadIdx.x; i < len4; i += 256){
    float4 v = p4[i];
    m = fmaxf(m, fmaxf(fmaxf(v.x, v.y), fmaxf(v.z, v.w)));
  }
  for (int i = (len4 << 2) + threadIdx.x; i < len; i += 256) m = fmaxf(m, p[i]);
  m = blk_reduce(m, true);

  float s = 0.f;
  for (int i = threadIdx.x; i < len4; i += 256){
    float4 v = p4[i];
    v.x = __expf(v.x - m); v.y = __expf(v.y - m);
    v.z = __expf(v.z - m); v.w = __expf(v.w - m);
    p4[i] = v;
    s += (v.x + v.y) + (v.z + v.w);
  }
  for (int i = (len4 << 2) + threadIdx.x; i < len; i += 256){
    float e = __expf(p[i] - m);
    p[i] = e;
    s += e;
  }
  s = blk_reduce(s, false);
  const float inv = 1.f / s;

  for (int i = threadIdx.x; i < len4; i += 256){
    float4 v = p4[i];
    v.x = tf32r(v.x * inv); v.y = tf32r(v.y * inv);
    v.z = tf32r(v.z * inv); v.w = tf32r(v.w * inv);
    p4[i] = v;
  }
  for (int i = (len4 << 2) + threadIdx.x; i < len; i += 256) p[i] = tf32r(p[i] * inv);

  const int lenUp = (len + 127) & ~127;
  for (int i = len + threadIdx.x; i < lenUp; i += 256) p[i] = 0.f;
}

// ---------------------------------------------------------------------------
extern "C" void kernel_launch(void* const* d_in, const int* in_sizes, int n_in,
                              void* d_out, int out_size)
{
  const float* x = (const float*)d_in[0];
  const float* W = (const float*)d_in[1];
  float* out = (float*)d_out;

  const int SMEM_BF   = 2 * BT_STAGE;      // 81920
  const int SMEM_TF   = 4 * 2 * TILE_B;    // 81920
  cudaFuncSetAttribute(k_proj,   cudaFuncAttributeMaxDynamicSharedMemorySize, SMEM_BF);
  cudaFuncSetAttribute(k_scores, cudaFuncAttributeMaxDynamicSharedMemorySize, SMEM_BF);
  cudaFuncSetAttribute(k_out_tc, cudaFuncAttributeMaxDynamicSharedMemorySize, SMEM_TF);

  cudaMemsetAsync(out, 0, (size_t)out_size * sizeof(float), 0);

  k_prep   <<<1184, 256>>>(x, W);
  k_proj   <<<dim3(4, 64),       256, SMEM_BF>>>();
  k_scores <<<dim3(32, 32, NB),  256, SMEM_BF>>>();
  k_softmax<<<NB * NCTX, 256>>>();
  k_out_tc <<<dim3(4, 32, NB*4), 256, SMEM_TF>>>(x, out);
}

// round 7
// speedup vs baseline: 1.5095x; 1.0048x over previous
#include <cuda_runtime.h>
#include <cuda_bf16.h>
#include <cstdint>

#define NCTX 4096
#define DM   512
#define NB   2
#define LDKT (NB*NCTX)

// Scratch
__device__ __nv_bfloat16 g_xhi[(size_t)NB*NCTX*DM];
__device__ __nv_bfloat16 g_xlo[(size_t)NB*NCTX*DM];
__device__ __nv_bfloat16 g_Whi[(size_t)DM*DM];
__device__ __nv_bfloat16 g_Wlo[(size_t)DM*DM];
__device__ __nv_bfloat16 g_Khi[(size_t)NB*NCTX*DM];
__device__ __nv_bfloat16 g_Klo[(size_t)NB*NCTX*DM];
__device__ float g_Kt [(size_t)DM*NB*NCTX];    // tf32-rounded K^T
__device__ float g_S  [(size_t)NB*NCTX*NCTX];  // scores -> unnormalized probs
__device__ float g_inv[(size_t)NB*NCTX];       // 1 / rowsum(exp)

// ---------------------------------------------------------------------------
// helpers
// ---------------------------------------------------------------------------
__device__ __forceinline__ uint32_t s2u(const void* p){
  uint32_t a;
  asm("{ .reg .u64 t; cvta.to.shared.u64 t, %1; cvt.u32.u64 %0, t; }" : "=r"(a) : "l"(p));
  return a;
}
__device__ __forceinline__ float tf32r(float x){
  uint32_t u; asm("cvt.rna.tf32.f32 %0, %1;" : "=r"(u) : "f"(x));
  return __uint_as_float(u);
}
__device__ __forceinline__ void ldsm4(uint32_t* r, uint32_t addr){
  asm volatile("ldmatrix.sync.aligned.m8n8.x4.shared.b16 {%0,%1,%2,%3}, [%4];"
    : "=r"(r[0]), "=r"(r[1]), "=r"(r[2]), "=r"(r[3]) : "r"(addr));
}
__device__ __forceinline__ void mma8(float* c, const uint32_t* a, const uint32_t* b){
  asm volatile("mma.sync.aligned.m16n8k8.row.col.f32.tf32.tf32.f32 "
    "{%0,%1,%2,%3}, {%4,%5,%6,%7}, {%8,%9}, {%0,%1,%2,%3};"
    : "+f"(c[0]), "+f"(c[1]), "+f"(c[2]), "+f"(c[3])
    : "r"(a[0]), "r"(a[1]), "r"(a[2]), "r"(a[3]), "r"(b[0]), "r"(b[1]));
}
__device__ __forceinline__ void bmma(float* c, const uint32_t* a, const uint32_t* b){
  asm volatile("mma.sync.aligned.m16n8k16.row.col.f32.bf16.bf16.f32 "
    "{%0,%1,%2,%3}, {%4,%5,%6,%7}, {%8,%9}, {%0,%1,%2,%3};"
    : "+f"(c[0]), "+f"(c[1]), "+f"(c[2]), "+f"(c[3])
    : "r"(a[0]), "r"(a[1]), "r"(a[2]), "r"(a[3]), "r"(b[0]), "r"(b[1]));
}
__device__ __forceinline__ void cp16(uint32_t d, const void* s){
  asm volatile("cp.async.cg.shared.global [%0], [%1], 16;" :: "r"(d), "l"(s));
}
__device__ __forceinline__ void cp_commit(){
  asm volatile("cp.async.commit_group;" ::: "memory");
}
template<int N> __device__ __forceinline__ void cp_wait(){
  asm volatile("cp.async.wait_group %0;" :: "n"(N) : "memory");
}

// ===========================================================================
// bf16 split (3-MMA) GEMM: C[128x128] = A * B^T  (hi/lo pre-decomposed)
// ===========================================================================
#define BT_TILE  10240
#define BT_STAGE (4*BT_TILE)

template<class EPI>
__device__ __forceinline__ void bgemm_split(
    const __nv_bfloat16* __restrict__ Ah, const __nv_bfloat16* __restrict__ Al, int lda,
    const __nv_bfloat16* __restrict__ Bh, const __nv_bfloat16* __restrict__ Bl, int ldb,
    int m0, int n0, int k1, EPI&& epi)
{
  extern __shared__ __align__(16) char sd[];
  const int t = threadIdx.x, l = t & 31, w = t >> 5;
  const int wm = w & 3, wn = w >> 2;
  const int row = t >> 1, seg = (t & 1) * 16;
  const uint32_t sb = s2u(sd);
  const uint32_t soff = (uint32_t)row*80 + (t & 1)*32;

  const __nv_bfloat16* pAh = Ah + (size_t)(m0 + row)*lda + seg;
  const __nv_bfloat16* pAl = Al + (size_t)(m0 + row)*lda + seg;
  const __nv_bfloat16* pBh = Bh + (size_t)(n0 + row)*ldb + seg;
  const __nv_bfloat16* pBl = Bl + (size_t)(n0 + row)*ldb + seg;

  const int nch = k1 >> 5;
  auto load_stage = [&](int c){
    const int kb = c << 5;
    const uint32_t st = sb + (c & 1)*BT_STAGE + soff;
    cp16(st,               pAh + kb); cp16(st + 16,             pAh + kb + 8);
    cp16(st +   BT_TILE,   pAl + kb); cp16(st +   BT_TILE + 16, pAl + kb + 8);
    cp16(st + 2*BT_TILE,   pBh + kb); cp16(st + 2*BT_TILE + 16, pBh + kb + 8);
    cp16(st + 3*BT_TILE,   pBl + kb); cp16(st + 3*BT_TILE + 16, pBl + kb + 8);
  };
  load_stage(0);
  cp_commit();

  const uint32_t aoff = (uint32_t)(wm*32 + (l & 15))*80 + ((l >> 4) & 1)*16;
  const uint32_t boff = (uint32_t)(wn*64 + (l & 7) + ((l >> 4) & 1)*8)*80
                      + ((l >> 3) & 1)*16;

  float acc[2][8][4] = {};

  for (int c = 0; c < nch; c++){
    cp_wait<0>();
    __syncthreads();
    if (c + 1 < nch) load_stage(c + 1);
    cp_commit();

    const uint32_t base = sb + (c & 1)*BT_STAGE;
    const uint32_t uAh = base + aoff,             uAl = uAh + BT_TILE;
    const uint32_t uBh = base + 2*BT_TILE + boff, uBl = uBh + BT_TILE;

    #pragma unroll
    for (int kf = 0; kf < 2; kf++){
      const uint32_t ko = kf*32;
      uint32_t ah[2][4], al[2][4];
      ldsm4(ah[0], uAh + ko);  ldsm4(ah[1], uAh + ko + 16*80);
      ldsm4(al[0], uAl + ko);  ldsm4(al[1], uAl + ko + 16*80);
      #pragma unroll
      for (int nf2 = 0; nf2 < 4; nf2++){
        uint32_t bh[4], bl[4];
        ldsm4(bh, uBh + ko + nf2*16*80);
        ldsm4(bl, uBl + ko + nf2*16*80);
        #pragma unroll
        for (int mf = 0; mf < 2; mf++){
          bmma(acc[mf][2*nf2],     ah[mf], bh);
          bmma(acc[mf][2*nf2 + 1], ah[mf], bh + 2);
          bmma(acc[mf][2*nf2],     ah[mf], bl);
          bmma(acc[mf][2*nf2 + 1], ah[mf], bl + 2);
          bmma(acc[mf][2*nf2],     al[mf], bh);
          bmma(acc[mf][2*nf2 + 1], al[mf], bh + 2);
        }
      }
    }
  }
  epi(acc);
}

// ===========================================================================
// tf32 single GEMM (P @ K), fp32 inputs, multi-stage cp.async
// ===========================================================================
#define TILE_B  (128*20*4)
#define MFRAG_B (16*20*4)

template<int STAGES, class EPI>
__device__ __forceinline__ void tgemm(
    const float* __restrict__ A, int lda,
    const float* __restrict__ B, int ldb,
    int m0, int n0, int k0, int k1, EPI&& epi)
{
  extern __shared__ __align__(16) char sd[];
  const int STAGE = 2*TILE_B;
  const int t = threadIdx.x, l = t & 31, w = t >> 5;
  const int wm = w & 3, wn = w >> 2;
  const int arow = t >> 1, acol = (t & 1) * 8;
  const uint32_t soff = (uint32_t)(arow*20 + acol) * 4;
  const uint32_t sb = s2u(sd);

  const float* pA = A + (size_t)(m0 + arow)*lda + acol;
  const float* pB = B + (size_t)(n0 + arow)*ldb + acol;

  const int nch = (k1 - k0) >> 4;
  auto load_stage = [&](int c){
    const int kb = k0 + (c << 4);
    const uint32_t st  = sb + (c % STAGES)*STAGE + soff;
    cp16(st,            pA + kb);  cp16(st + 16,          pA + kb + 4);
    cp16(st + TILE_B,   pB + kb);  cp16(st + TILE_B + 16, pB + kb + 4);
  };
  #pragma unroll
  for (int s = 0; s < STAGES-1; s++){
    if (s < nch) load_stage(s);
    cp_commit();
  }

  const int rowA = (l & 7) + ((l >> 3) & 1) * 8;
  const int colA = ((l >> 4) & 1) * 4;
  const int rowB = (l & 7) + ((l >> 4) & 1) * 8;
  const int colB = ((l >> 3) & 1) * 4;
  const uint32_t aoff = (uint32_t)((wm*32 + rowA)*20 + colA) * 4;
  const uint32_t boff = (uint32_t)((wn*64 + rowB)*20 + colB) * 4;

  float acc[2][8][4] = {};

  for (int c = 0; c < nch; c++){
    cp_wait<STAGES-2>();
    __syncthreads();
    const int cn = c + STAGES - 1;
    if (cn < nch) load_stage(cn);
    cp_commit();

    const uint32_t base = sb + (c % STAGES)*STAGE;
    const uint32_t uA = base + aoff;
    const uint32_t uB = base + TILE_B + boff;

    #pragma unroll
    for (int kf = 0; kf < 2; kf++){
      const uint32_t ko = kf * 32;
      uint32_t a[2][4];
      ldsm4(a[0], uA + ko);
      ldsm4(a[1], uA + ko + MFRAG_B);
      #pragma unroll
      for (int nf2 = 0; nf2 < 4; nf2++){
        uint32_t b[4];
        ldsm4(b, uB + ko + nf2 * MFRAG_B);
        #pragma unroll
        for (int mf = 0; mf < 2; mf++){
          mma8(acc[mf][2*nf2],     a[mf], b);
          mma8(acc[mf][2*nf2 + 1], a[mf], b + 2);
        }
      }
    }
  }
  epi(acc);
}

// plain store epilogue
__device__ __forceinline__ void epi_store(float (&acc)[2][8][4],
                                          float* __restrict__ C, int ldc,
                                          int m0, int n0)
{
  const int t = threadIdx.x, l = t & 31, w = t >> 5;
  const int wm = w & 3, wn = w >> 2;
  #pragma unroll
  for (int mf = 0; mf < 2; mf++){
    const int r0 = m0 + wm*32 + mf*16 + (l >> 2);
    #pragma unroll
    for (int nf = 0; nf < 8; nf++){
      const int cc = n0 + wn*64 + nf*8 + 2*(l & 3);
      *(float2*)&C[(size_t)r0*ldc + cc]     = make_float2(acc[mf][nf][0], acc[mf][nf][1]);
      *(float2*)&C[(size_t)(r0+8)*ldc + cc] = make_float2(acc[mf][nf][2], acc[mf][nf][3]);
    }
  }
}

// ---------------------------------------------------------------------------
// Kernels
// ---------------------------------------------------------------------------
__global__ void __launch_bounds__(256)
k_prep(const float* __restrict__ x, const float* __restrict__ W)
{
  const size_t nx = (size_t)NB*NCTX*DM/4, nw = (size_t)DM*DM/4;
  for (size_t i = blockIdx.x*256 + threadIdx.x; i < nx + nw; i += (size_t)gridDim.x*256){
    float4 v;
    __nv_bfloat16* hi; __nv_bfloat16* lo; size_t j;
    if (i < nx){ v = ((const float4*)x)[i];      hi = g_xhi; lo = g_xlo; j = i; }
    else       { v = ((const float4*)W)[i - nx]; hi = g_Whi; lo = g_Wlo; j = i - nx; }
    __nv_bfloat16 hx = __float2bfloat16_rn(v.x), hy = __float2bfloat16_rn(v.y);
    __nv_bfloat16 hz = __float2bfloat16_rn(v.z), hw = __float2bfloat16_rn(v.w);
    __nv_bfloat162 h01; h01.x = hx; h01.y = hy;
    __nv_bfloat162 h23; h23.x = hz; h23.y = hw;
    __nv_bfloat162 l01; l01.x = __float2bfloat16_rn(v.x - __bfloat162float(hx));
                        l01.y = __float2bfloat16_rn(v.y - __bfloat162float(hy));
    __nv_bfloat162 l23; l23.x = __float2bfloat16_rn(v.z - __bfloat162float(hz));
                        l23.y = __float2bfloat16_rn(v.w - __bfloat162float(hw));
    ((__nv_bfloat162*)hi)[2*j]     = h01;
    ((__nv_bfloat162*)hi)[2*j + 1] = h23;
    ((__nv_bfloat162*)lo)[2*j]     = l01;
    ((__nv_bfloat162*)lo)[2*j + 1] = l23;
  }
}

__global__ void __launch_bounds__(256, 2)
k_proj()
{
  const int n0 = blockIdx.x*128, m0 = blockIdx.y*128;
  bgemm_split(g_xhi, g_xlo, DM, g_Whi, g_Wlo, DM, m0, n0, DM,
    [&](float (&acc)[2][8][4]){
      const int t = threadIdx.x, l = t & 31, w = t >> 5;
      const int wm = w & 3, wn = w >> 2;
      #pragma unroll
      for (int mf = 0; mf < 2; mf++){
        const int r0 = m0 + wm*32 + mf*16 + (l >> 2);
        #pragma unroll
        for (int nf = 0; nf < 8; nf++){
          const int cc = n0 + wn*64 + nf*8 + 2*(l & 3);
          #pragma unroll
          for (int hh = 0; hh < 2; hh++){
            const int r = r0 + hh*8;
            const float v0 = acc[mf][nf][2*hh], v1 = acc[mf][nf][2*hh+1];
            __nv_bfloat16 h0 = __float2bfloat16_rn(v0), h1 = __float2bfloat16_rn(v1);
            __nv_bfloat162 hp; hp.x = h0; hp.y = h1;
            __nv_bfloat162 lp;
            lp.x = __float2bfloat16_rn(v0 - __bfloat162float(h0));
            lp.y = __float2bfloat16_rn(v1 - __bfloat162float(h1));
            const size_t ki = (size_t)r*DM + cc;
            *(__nv_bfloat162*)&g_Khi[ki] = hp;
            *(__nv_bfloat162*)&g_Klo[ki] = lp;
            g_Kt[(size_t)cc    *LDKT + r] = tf32r(v0);
            g_Kt[(size_t)(cc+1)*LDKT + r] = tf32r(v1);
          }
        }
      }
    });
}

__global__ void __launch_bounds__(256, 2)
k_scores()
{
  const int b  = blockIdx.z;
  const int n0 = blockIdx.x*128, m0 = blockIdx.y*128;
  if (n0 > m0) return;
  const size_t off = (size_t)b*NCTX*DM;
  float* Sb = g_S + (size_t)b*NCTX*NCTX;
  bgemm_split(g_xhi + off, g_xlo + off, DM, g_Khi + off, g_Klo + off, DM,
    m0, n0, DM,
    [&](float (&acc)[2][8][4]){ epi_store(acc, Sb, NCTX, m0, n0); });
}

// ---------------------------------------------------------------------------
// softmax (no max-subtraction; defer normalization): S <- tf32(exp(S)),
// g_inv[row] = 1/rowsum. Then zero-pad the tile remainder.
// ---------------------------------------------------------------------------
__device__ __forceinline__ float blk_sum(float v)
{
  __shared__ float sm[8];
  const int lane = threadIdx.x & 31, w = threadIdx.x >> 5;
  #pragma unroll
  for (int o = 16; o; o >>= 1) v += __shfl_xor_sync(0xffffffffu, v, o);
  if (lane == 0) sm[w] = v;
  __syncthreads();
  float r = sm[0];
  #pragma unroll
  for (int i = 1; i < 8; i++) r += sm[i];
  return r;
}

__global__ void __launch_bounds__(256)
k_softmax()
{
  const int row = blockIdx.x;           // == b*NCTX + q
  const int q   = row & (NCTX - 1);
  float* p = g_S + (size_t)row * NCTX;
  const int len  = q + 1;
  const int len4 = len >> 2;
  float4* p4 = (float4*)p;

  float s = 0.f;
  for (int i = threadIdx.x; i < len4; i += 256){
    float4 v = p4[i];
    v.x = __expf(v.x); v.y = __expf(v.y);
    v.z = __expf(v.z); v.w = __expf(v.w);
    s += (v.x + v.y) + (v.z + v.w);
    v.x = tf32r(v.x); v.y = tf32r(v.y);
    v.z = tf32r(v.z); v.w = tf32r(v.w);
    p4[i] = v;
  }
  for (int i = (len4 << 2) + threadIdx.x; i < len; i += 256){
    float e = __expf(p[i]);
    s += e;
    p[i] = tf32r(e);
  }
  s = blk_sum(s);
  if (threadIdx.x == 0) g_inv[row] = 1.f / s;

  const int lenUp = (len + 127) & ~127;
  for (int i = len + threadIdx.x; i < lenUp; i += 256) p[i] = 0.f;
}

// ---------------------------------------------------------------------------
// out = x + (P @ K) * inv, no split-K, no atomics. CTA pairs m-tiles i and
// 31-i so per-CTA causal work is identical (33*8 chunks). 128 CTAs total.
// ---------------------------------------------------------------------------
__global__ void __launch_bounds__(256)
k_out_tc(const float* __restrict__ x, float* __restrict__ out)
{
  const int b    = blockIdx.z;
  const int n0   = blockIdx.x*128;
  const int pair = blockIdx.y;          // 0..15
  const float* Pb = g_S  + (size_t)b*NCTX*NCTX;
  const float* Bt = g_Kt + (size_t)b*NCTX;

  #pragma unroll
  for (int s = 0; s < 2; s++){
    const int i  = s ? (31 - pair) : pair;
    const int m0 = i*128;
    tgemm<4>(Pb, NCTX, Bt, LDKT, m0, n0, 0, m0 + 128,
      [&](float (&acc)[2][8][4]){
        const int t = threadIdx.x, l = t & 31, w = t >> 5;
        const int wm = w & 3, wn = w >> 2;
        #pragma unroll
        for (int mf = 0; mf < 2; mf++){
          const int r0 = m0 + wm*32 + mf*16 + (l >> 2);
          const float inv0 = g_inv[b*NCTX + r0];
          const float inv1 = g_inv[b*NCTX + r0 + 8];
          #pragma unroll
          for (int nf = 0; nf < 8; nf++){
            const int cc = n0 + wn*64 + nf*8 + 2*(l & 3);
            const size_t i0 = (size_t)b*NCTX*DM + (size_t)r0*DM + cc;
            const size_t i1 = i0 + (size_t)8*DM;
            *(float2*)&out[i0] = make_float2(acc[mf][nf][0]*inv0 + x[i0],
                                             acc[mf][nf][1]*inv0 + x[i0+1]);
            *(float2*)&out[i1] = make_float2(acc[mf][nf][2]*inv1 + x[i1],
                                             acc[mf][nf][3]*inv1 + x[i1+1]);
          }
        }
      });
  }
}

// ---------------------------------------------------------------------------
extern "C" void kernel_launch(void* const* d_in, const int* in_sizes, int n_in,
                              void* d_out, int out_size)
{
  const float* x = (const float*)d_in[0];
  const float* W = (const float*)d_in[1];
  float* out = (float*)d_out;

  const int SMEM_BF = 2 * BT_STAGE;      // 81920
  const int SMEM_TF = 4 * 2 * TILE_B;    // 81920
  cudaFuncSetAttribute(k_proj,   cudaFuncAttributeMaxDynamicSharedMemorySize, SMEM_BF);
  cudaFuncSetAttribute(k_scores, cudaFuncAttributeMaxDynamicSharedMemorySize, SMEM_BF);
  cudaFuncSetAttribute(k_out_tc, cudaFuncAttributeMaxDynamicSharedMemorySize, SMEM_TF);

  k_prep   <<<1184, 256>>>(x, W);
  k_proj   <<<dim3(4, 64),      256, SMEM_BF>>>();
  k_scores <<<dim3(32, 32, NB), 256, SMEM_BF>>>();
  k_softmax<<<NB * NCTX, 256>>>();
  k_out_tc <<<dim3(4, 16, NB),  256, SMEM_TF>>>(x, out);
}